// round 13
// baseline (speedup 1.0000x reference)
#include <cuda_runtime.h>
#include <cuda_bf16.h>
#include <math.h>
#include <stdint.h>

// Problem constants
#define E_      8
#define S_      512
#define DIM_    1024
#define DFF_    2730
#define DFF2_   5460
#define VOCAB_  32000
#define NPAIR   1024   // S_ * 2

// ------------------------- device scratch (device-code access only) ----------
__device__ int   g_done;
__device__ int   g_cnt[E_];
__device__ int   g_rows[E_][NPAIR];
__device__ int   g_eid[NPAIR];
__device__ float g_gate[NPAIR];
__device__ float g_lse[NPAIR];
__device__ float g_h1[(size_t)NPAIR * DFF_];
__device__ float g_h2[(size_t)NPAIR * DIM_];
__device__ float g_logits[(size_t)NPAIR * VOCAB_];

// ------------------------- PTX helpers (sm_80-era, plain sm_103-safe) --------
__device__ __forceinline__ uint32_t smem_u32(const void* p) {
    uint32_t a;
    asm("{ .reg .u64 t; cvta.to.shared.u64 t, %1; cvt.u32.u64 %0, t; }"
        : "=r"(a) : "l"(p));
    return a;
}
#define CPA16(dst, src) \
    asm volatile("cp.async.cg.shared.global [%0], [%1], 16;" :: "r"(dst), "l"(src))
#define CPA8(dst, src) \
    asm volatile("cp.async.ca.shared.global [%0], [%1], 8;" :: "r"(dst), "l"(src))
#define CPA_COMMIT() asm volatile("cp.async.commit_group;" ::: "memory")
#define CPA_WAIT(n)  asm volatile("cp.async.wait_group %0;" :: "n"(n) : "memory")

__device__ __forceinline__ uint32_t packbf(float lo, float hi) {
    uint32_t r;
    asm("cvt.rn.bf16x2.f32 %0, %1, %2;" : "=r"(r) : "f"(hi), "f"(lo));
    return r;
}
__device__ __forceinline__ void mma_bf16(float* d, const uint32_t* a, const uint32_t* b) {
    asm volatile(
        "mma.sync.aligned.m16n8k16.row.col.f32.bf16.bf16.f32 "
        "{%0,%1,%2,%3}, {%4,%5,%6,%7}, {%8,%9}, {%0,%1,%2,%3};"
        : "+f"(d[0]), "+f"(d[1]), "+f"(d[2]), "+f"(d[3])
        : "r"(a[0]), "r"(a[1]), "r"(a[2]), "r"(a[3]), "r"(b[0]), "r"(b[1]));
}

// ------------------------- router + fused grouping -------------------------
__global__ void router_kernel(const float* __restrict__ x,
                              const float* __restrict__ Wr) {
    int s = blockIdx.x;
    const float* xr = x + (size_t)s * DIM_;
    float acc[E_];
#pragma unroll
    for (int e = 0; e < E_; e++) acc[e] = 0.f;
    for (int d = threadIdx.x; d < DIM_; d += blockDim.x) {
        float xv = xr[d];
#pragma unroll
        for (int e = 0; e < E_; e++) acc[e] = fmaf(xv, Wr[e * DIM_ + d], acc[e]);
    }
    __shared__ float red[256];
    __shared__ float score[E_];
#pragma unroll
    for (int e = 0; e < E_; e++) {
        red[threadIdx.x] = acc[e];
        __syncthreads();
        for (int st = 128; st > 0; st >>= 1) {
            if (threadIdx.x < st) red[threadIdx.x] += red[threadIdx.x + st];
            __syncthreads();
        }
        if (threadIdx.x == 0) score[e] = red[0];
        __syncthreads();
    }
    if (threadIdx.x == 0) {
        int i0 = 0; float s0 = score[0];
        for (int e = 1; e < E_; e++) if (score[e] > s0) { s0 = score[e]; i0 = e; }
        int i1 = -1; float s1 = -INFINITY;
        for (int e = 0; e < E_; e++) {
            if (e == i0) continue;
            if (score[e] > s1) { s1 = score[e]; i1 = e; }
        }
        float m   = fmaxf(s0, s1);
        float lse = m + logf(expf(s0 - m) + expf(s1 - m));
        int p0 = 2 * s, p1 = 2 * s + 1;
        g_gate[p0] = s0 - lse;  g_gate[p1] = s1 - lse;
        g_eid[p0]  = i0;        g_eid[p1]  = i1;
    }

    __shared__ int amLast;
    __threadfence();
    if (threadIdx.x == 0) {
        int t = atomicAdd(&g_done, 1);
        amLast = (t == S_ - 1) ? 1 : 0;
    }
    __syncthreads();
    if (amLast) {
        __threadfence();
        int w = threadIdx.x / 32, lane = threadIdx.x % 32;
        if (w < E_) {
            int count = 0;
            for (int base = 0; base < NPAIR; base += 32) {
                int p  = base + lane;
                int id = g_eid[p];
                unsigned mask = __ballot_sync(0xffffffffu, id == w);
                if (id == w)
                    g_rows[w][count + __popc(mask & ((1u << lane) - 1u))] = p;
                count += __popc(mask);
            }
            if (lane == 0) g_cnt[w] = count;
        }
        if (threadIdx.x == 0) g_done = 0;
        __threadfence();
    }
}

// ------------------------- bf16 mma.sync grouped GEMM, 3-stage ring ----------
// Block tile 256x128 (tall-M: each expert's weights stream ONCE), BK=32,
// 8 warps (4x2), warp tile 64x64, m16n8k16 bf16.
// mode 0: C = A@W^T (+bias +resid), scatter rows.
// mode 1: up+SwiGLU fused (interleaved h/gate B-row gather, gelu in epilogue).
#define TM 256
#define TN 128
#define BK 32
#define NSTAGE 3
#define LDS_STRIDE 40
#define A_TILE_F (256 * LDS_STRIDE)
#define B_TILE_F (128 * LDS_STRIDE)
#define STAGE_F  (A_TILE_F + B_TILE_F)
#define GEMM_SMEM (NSTAGE * STAGE_F * 4)   // 184,320 B

__global__ __launch_bounds__(256, 1)
void gemm_tc_kernel(const float* __restrict__ Aext,
                    const float* __restrict__ Bw,
                    const float* __restrict__ bias,
                    const float* __restrict__ resid,
                    int a_sel, int out_sel, int mode,
                    int Kdim, int Nt, int row_shift) {
    extern __shared__ float sm[];
    const float* A   = (a_sel == 0) ? Aext : (a_sel == 1 ? g_h1 : g_h2);
    float*       Out = (out_sel == 1) ? g_h1 : (out_sel == 2 ? g_h2 : g_logits);

    int e   = blockIdx.z;
    int cnt = g_cnt[e];
    int m0  = blockIdx.y * TM;
    if (m0 >= cnt) return;
    int n0  = blockIdx.x * TN;

    const float* Bexp = Bw + (size_t)e * Nt * Kdim;
    const int*   rows = g_rows[e];
    int tid = threadIdx.x, wid = tid >> 5, lane = tid & 31;

    const bool f4 = ((Kdim & 3) == 0);
    const int  nch = (Kdim + BK - 1) / BK;

    auto brow_ptr = [&](int gn, bool& ok) -> const float* {
        if (mode == 1) {
            int f = gn >> 1;
            ok = (f < DFF_);
            size_t r = (gn & 1) ? (size_t)(DFF_ + f) : (size_t)f;
            return Bexp + r * Kdim;
        }
        ok = (gn < Nt);
        return Bexp + (size_t)gn * Kdim;
    };

    auto load_tile = [&](int i, int s) {
        int k0 = i * BK;
        float* Ab = sm + s * STAGE_F;
        float* Bb = Ab + A_TILE_F;
        uint32_t Au = smem_u32(Ab), Bu = smem_u32(Bb);
        if (f4) {
            for (int u = tid; u < 256 * 8; u += 256) {   // A: 256 rows x 8 float4
                int r = u >> 3, c = u & 7, kg = k0 + c * 4;
                int gm = m0 + r;
                uint32_t dA = Au + (uint32_t)(r * LDS_STRIDE + c * 4) * 4u;
                if (gm < cnt) {
                    int pr = rows[gm];
                    int rr = row_shift ? (pr >> 1) : pr;
                    CPA16(dA, A + (size_t)rr * Kdim + kg);
                } else {
                    *(float4*)(Ab + r * LDS_STRIDE + c * 4) = make_float4(0, 0, 0, 0);
                }
            }
            for (int u = tid; u < 128 * 8; u += 256) {   // B: 128 rows x 8 float4
                int r = u >> 3, c = u & 7, kg = k0 + c * 4;
                bool ok; const float* src = brow_ptr(n0 + r, ok);
                uint32_t dB = Bu + (uint32_t)(r * LDS_STRIDE + c * 4) * 4u;
                if (ok) CPA16(dB, src + kg);
                else    *(float4*)(Bb + r * LDS_STRIDE + c * 4) = make_float4(0, 0, 0, 0);
            }
        } else {
            for (int u = tid; u < 256 * 16; u += 256) {
                int r = u >> 4, c = u & 15, kg = k0 + c * 2;
                int gm = m0 + r;
                uint32_t dA = Au + (uint32_t)(r * LDS_STRIDE + c * 2) * 4u;
                if (gm < cnt && kg < Kdim) {
                    int pr = rows[gm];
                    int rr = row_shift ? (pr >> 1) : pr;
                    CPA8(dA, A + (size_t)rr * Kdim + kg);
                } else {
                    *(float2*)(Ab + r * LDS_STRIDE + c * 2) = make_float2(0, 0);
                }
            }
            for (int u = tid; u < 128 * 16; u += 256) {
                int r = u >> 4, c = u & 15, kg = k0 + c * 2;
                bool ok; const float* src = brow_ptr(n0 + r, ok);
                uint32_t dB = Bu + (uint32_t)(r * LDS_STRIDE + c * 2) * 4u;
                if (ok && kg < Kdim) CPA8(dB, src + kg);
                else *(float2*)(Bb + r * LDS_STRIDE + c * 2) = make_float2(0, 0);
            }
        }
    };

    // warp layout: 4 (m) x 2 (n); warp tile 64 x 64
    int wy = wid >> 1, wx = wid & 1;
    int mw = wy * 64, nw = wx * 64;
    int lr = lane >> 2, lc = lane & 3;

    float acc[4][8][4];
#pragma unroll
    for (int i = 0; i < 4; i++)
#pragma unroll
        for (int j = 0; j < 8; j++)
#pragma unroll
            for (int q = 0; q < 4; q++) acc[i][j][q] = 0.f;

    load_tile(0, 0);
    CPA_COMMIT();
    if (nch > 1) load_tile(1, 1);
    CPA_COMMIT();

    for (int it = 0; it < nch; it++) {
        CPA_WAIT(1);
        __syncthreads();

        if (it + 2 < nch) load_tile(it + 2, (it + 2) % NSTAGE);
        CPA_COMMIT();

        const float* As = sm + (it % NSTAGE) * STAGE_F;
        const float* Bs = As + A_TILE_F;
#pragma unroll
        for (int ks = 0; ks < BK; ks += 16) {
            uint32_t af[4][4], bf[8][2];
#pragma unroll
            for (int mt = 0; mt < 4; mt++) {
                const float* p = As + (mw + mt * 16 + lr) * LDS_STRIDE + ks + 2 * lc;
                float2 v0 = *(const float2*)(p);
                float2 v1 = *(const float2*)(p + 8 * LDS_STRIDE);
                float2 v2 = *(const float2*)(p + 8);
                float2 v3 = *(const float2*)(p + 8 * LDS_STRIDE + 8);
                af[mt][0] = packbf(v0.x, v0.y);
                af[mt][1] = packbf(v1.x, v1.y);
                af[mt][2] = packbf(v2.x, v2.y);
                af[mt][3] = packbf(v3.x, v3.y);
            }
#pragma unroll
            for (int nt = 0; nt < 8; nt++) {
                const float* q = Bs + (nw + nt * 8 + lr) * LDS_STRIDE + ks + 2 * lc;
                float2 u0 = *(const float2*)(q);
                float2 u1 = *(const float2*)(q + 8);
                bf[nt][0] = packbf(u0.x, u0.y);
                bf[nt][1] = packbf(u1.x, u1.y);
            }
#pragma unroll
            for (int mt = 0; mt < 4; mt++)
#pragma unroll
                for (int nt = 0; nt < 8; nt++)
                    mma_bf16(acc[mt][nt], af[mt], bf[nt]);
        }
    }

    __syncthreads();

    // ---- epilogue ----
    if (mode == 1) {
        const float* bb = bias + (size_t)e * DFF2_;
#pragma unroll
        for (int mt = 0; mt < 4; mt++) {
#pragma unroll
            for (int half = 0; half < 2; half++) {
                int rg = m0 + mw + mt * 16 + lr + half * 8;
                if (rg >= cnt) continue;
                int pair = rows[rg];
                size_t obase = (size_t)pair * DFF_;
#pragma unroll
                for (int nt = 0; nt < 8; nt++) {
                    int cg = n0 + nw + nt * 8 + 2 * lc;   // even col
                    int f  = cg >> 1;
                    if (f >= DFF_) continue;
                    float h = acc[mt][nt][half * 2 + 0] + bb[f];
                    float g = acc[mt][nt][half * 2 + 1] + bb[DFF_ + f];
                    float ge = 0.5f * g * (1.f + erff(g * 0.70710678118654752440f));
                    Out[obase + f] = h * ge;
                }
            }
        }
    } else {
        const float* bb = bias ? bias + (size_t)e * Nt : nullptr;
#pragma unroll
        for (int mt = 0; mt < 4; mt++) {
#pragma unroll
            for (int half = 0; half < 2; half++) {
                int rg = m0 + mw + mt * 16 + lr + half * 8;
                if (rg >= cnt) continue;
                int pair = rows[rg];
                size_t obase = (size_t)pair * Nt;
                const float* rr = resid ? resid + (size_t)(pair >> 1) * Nt : nullptr;
#pragma unroll
                for (int nt = 0; nt < 8; nt++) {
                    int cg = n0 + nw + nt * 8 + 2 * lc;
#pragma unroll
                    for (int q = 0; q < 2; q++) {
                        int col = cg + q;
                        if (col >= Nt) continue;
                        float v = acc[mt][nt][half * 2 + q];
                        if (bb) v += bb[col];
                        if (rr) v += rr[col];
                        Out[obase + col] = v;
                    }
                }
            }
        }
    }
}

// ------------------------- online logsumexp over vocab (single pass) ---------
__global__ void lse_kernel() {
    int p = blockIdx.x;
    const float* l = g_logits + (size_t)p * VOCAB_;
    int tid = threadIdx.x;
    float m = -INFINITY, s = 0.f;
    for (int v = tid; v < VOCAB_; v += 256) {
        float xv = l[v];
        if (xv > m) { s = s * expf(m - xv) + 1.f; m = xv; }
        else        { s += expf(xv - m); }
    }
    __shared__ float rm[256], rs[256];
    rm[tid] = m; rs[tid] = s;
    __syncthreads();
    for (int st = 128; st > 0; st >>= 1) {
        if (tid < st) {
            float m2 = rm[tid + st], s2 = rs[tid + st];
            float mm = fmaxf(rm[tid], m2);
            rs[tid] = rs[tid] * expf(rm[tid] - mm) + s2 * expf(m2 - mm);
            rm[tid] = mm;
        }
        __syncthreads();
    }
    if (tid == 0) g_lse[p] = rm[0] + logf(rs[0]);
}

// ------------------------- combine two experts per token ---------------------
__global__ void combine_kernel(float* __restrict__ out) {
    size_t idx = (size_t)blockIdx.x * blockDim.x + threadIdx.x;
    const size_t total = (size_t)S_ * VOCAB_;
    if (idx >= total) return;
    int s = (int)(idx / VOCAB_);
    int v = (int)(idx % VOCAB_);
    int p0 = 2 * s, p1 = 2 * s + 1;
    float a0 = g_logits[(size_t)p0 * VOCAB_ + v] + g_gate[p0] - g_lse[p0];
    float a1 = g_logits[(size_t)p1 * VOCAB_ + v] + g_gate[p1] - g_lse[p1];
    float m = fmaxf(a0, a1);
    out[idx] = m + logf(expf(a0 - m) + expf(a1 - m));
}

// ------------------------- launch -------------------------
extern "C" void kernel_launch(void* const* d_in, const int* in_sizes, int n_in,
                              void* d_out, int out_size) {
    const float *x = nullptr, *Wr = nullptr, *Wup = nullptr,
                *bup = nullptr, *Wdown = nullptr, *Wproj = nullptr;
    for (int i = 0; i < n_in; i++) {
        const float* p = (const float*)d_in[i];
        switch (in_sizes[i]) {
            case S_ * DIM_:            x     = p; break;
            case E_ * DIM_:            Wr    = p; break;
            case E_ * DFF2_ * DIM_:    Wup   = p; break;
            case E_ * DFF2_:           bup   = p; break;
            case E_ * DIM_ * DFF_:     Wdown = p; break;
            case E_ * VOCAB_ * DIM_:   Wproj = p; break;
        }
    }
    if (!x)     x     = (const float*)d_in[0];
    if (!Wr)    Wr    = (const float*)d_in[1];
    if (!Wup)   Wup   = (const float*)d_in[2];
    if (!bup)   bup   = (const float*)d_in[3];
    if (!Wdown) Wdown = (const float*)d_in[4];
    if (!Wproj) Wproj = (const float*)d_in[5];
    float* out = (float*)d_out;

    cudaFuncSetAttribute(gemm_tc_kernel,
                         cudaFuncAttributeMaxDynamicSharedMemorySize, GEMM_SMEM);

    // 1) router + fused grouping
    router_kernel<<<S_, 256>>>(x, Wr);

    // 2) up + fused SwiGLU: g_h1 = h * gelu(gate)
    {
        dim3 grid((DFF2_ + TN - 1) / TN, (NPAIR + TM - 1) / TM, E_);
        gemm_tc_kernel<<<grid, 256, GEMM_SMEM>>>(x, Wup, bup, nullptr,
                                                 0, 1, 1, DIM_, DFF2_, 1);
    }
    // 3) down + residual: g_h2 = g_h1 @ Wdown[e]^T + x
    {
        dim3 grid((DIM_ + TN - 1) / TN, (NPAIR + TM - 1) / TM, E_);
        gemm_tc_kernel<<<grid, 256, GEMM_SMEM>>>(nullptr, Wdown, nullptr, x,
                                                 1, 2, 0, DFF_, DIM_, 0);
    }
    // 4) proj: g_logits = g_h2 @ Wproj[e]^T   <-- ncu capture slot (#4)
    {
        dim3 grid((VOCAB_ + TN - 1) / TN, (NPAIR + TM - 1) / TM, E_);
        gemm_tc_kernel<<<grid, 256, GEMM_SMEM>>>(nullptr, Wproj, nullptr, nullptr,
                                                 2, 3, 0, DIM_, VOCAB_, 0);
    }
    // 5) per-pair LSE, 6) combine
    lse_kernel<<<NPAIR, 256>>>();
    {
        size_t total = (size_t)S_ * VOCAB_;
        combine_kernel<<<(int)((total + 255) / 256), 256>>>(out);
    }
}

// round 14
// speedup vs baseline: 1.2003x; 1.2003x over previous
#include <cuda_runtime.h>
#include <cuda_bf16.h>
#include <math.h>
#include <stdint.h>

// Problem constants
#define E_      8
#define S_      512
#define DIM_    1024
#define DFF_    2730
#define DFF2_   5460
#define VOCAB_  32000
#define NPAIR   1024   // S_ * 2

// ------------------------- device scratch (device-code access only) ----------
__device__ int   g_done;
__device__ int   g_cnt[E_];
__device__ int   g_rows[E_][NPAIR];
__device__ int   g_eid[NPAIR];
__device__ float g_gate[NPAIR];
__device__ float g_lse[NPAIR];
__device__ float g_h1[(size_t)NPAIR * DFF_];
__device__ float g_h2[(size_t)NPAIR * DIM_];
__device__ float g_logits[(size_t)NPAIR * VOCAB_];

// ------------------------- PTX helpers (sm_80-era, plain sm_103-safe) --------
__device__ __forceinline__ uint32_t smem_u32(const void* p) {
    uint32_t a;
    asm("{ .reg .u64 t; cvta.to.shared.u64 t, %1; cvt.u32.u64 %0, t; }"
        : "=r"(a) : "l"(p));
    return a;
}
#define CPA16(dst, src) \
    asm volatile("cp.async.cg.shared.global [%0], [%1], 16;" :: "r"(dst), "l"(src))
#define CPA8(dst, src) \
    asm volatile("cp.async.ca.shared.global [%0], [%1], 8;" :: "r"(dst), "l"(src))
#define CPA_COMMIT() asm volatile("cp.async.commit_group;" ::: "memory")
#define CPA_WAIT(n)  asm volatile("cp.async.wait_group %0;" :: "n"(n) : "memory")

__device__ __forceinline__ uint32_t packbf(float lo, float hi) {
    uint32_t r;
    asm("cvt.rn.bf16x2.f32 %0, %1, %2;" : "=r"(r) : "f"(hi), "f"(lo));
    return r;
}
__device__ __forceinline__ void mma_bf16(float* d, const uint32_t* a, const uint32_t* b) {
    asm volatile(
        "mma.sync.aligned.m16n8k16.row.col.f32.bf16.bf16.f32 "
        "{%0,%1,%2,%3}, {%4,%5,%6,%7}, {%8,%9}, {%0,%1,%2,%3};"
        : "+f"(d[0]), "+f"(d[1]), "+f"(d[2]), "+f"(d[3])
        : "r"(a[0]), "r"(a[1]), "r"(a[2]), "r"(a[3]), "r"(b[0]), "r"(b[1]));
}

// ------------------------- router + fused grouping -------------------------
__global__ void router_kernel(const float* __restrict__ x,
                              const float* __restrict__ Wr) {
    int s = blockIdx.x;
    const float* xr = x + (size_t)s * DIM_;
    float acc[E_];
#pragma unroll
    for (int e = 0; e < E_; e++) acc[e] = 0.f;
    for (int d = threadIdx.x; d < DIM_; d += blockDim.x) {
        float xv = xr[d];
#pragma unroll
        for (int e = 0; e < E_; e++) acc[e] = fmaf(xv, Wr[e * DIM_ + d], acc[e]);
    }
    __shared__ float red[256];
    __shared__ float score[E_];
#pragma unroll
    for (int e = 0; e < E_; e++) {
        red[threadIdx.x] = acc[e];
        __syncthreads();
        for (int st = 128; st > 0; st >>= 1) {
            if (threadIdx.x < st) red[threadIdx.x] += red[threadIdx.x + st];
            __syncthreads();
        }
        if (threadIdx.x == 0) score[e] = red[0];
        __syncthreads();
    }
    if (threadIdx.x == 0) {
        int i0 = 0; float s0 = score[0];
        for (int e = 1; e < E_; e++) if (score[e] > s0) { s0 = score[e]; i0 = e; }
        int i1 = -1; float s1 = -INFINITY;
        for (int e = 0; e < E_; e++) {
            if (e == i0) continue;
            if (score[e] > s1) { s1 = score[e]; i1 = e; }
        }
        float m   = fmaxf(s0, s1);
        float lse = m + logf(expf(s0 - m) + expf(s1 - m));
        int p0 = 2 * s, p1 = 2 * s + 1;
        g_gate[p0] = s0 - lse;  g_gate[p1] = s1 - lse;
        g_eid[p0]  = i0;        g_eid[p1]  = i1;
    }

    __shared__ int amLast;
    __threadfence();
    if (threadIdx.x == 0) {
        int t = atomicAdd(&g_done, 1);
        amLast = (t == S_ - 1) ? 1 : 0;
    }
    __syncthreads();
    if (amLast) {
        __threadfence();
        int w = threadIdx.x / 32, lane = threadIdx.x % 32;
        if (w < E_) {
            int count = 0;
            for (int base = 0; base < NPAIR; base += 32) {
                int p  = base + lane;
                int id = g_eid[p];
                unsigned mask = __ballot_sync(0xffffffffu, id == w);
                if (id == w)
                    g_rows[w][count + __popc(mask & ((1u << lane) - 1u))] = p;
                count += __popc(mask);
            }
            if (lane == 0) g_cnt[w] = count;
        }
        if (threadIdx.x == 0) g_done = 0;
        __threadfence();
    }
}

// ------------------------- bf16 mma.sync grouped GEMM, 3-stage ring ----------
// Block tile 128x256, BK=32, 8 warps (2x4), warp tile 64x64, m16n8k16 bf16.
// m-subtile skipping: 16-row groups beyond cnt skip fragment loads AND MMAs
// (warp-uniform branches) — removes padded-M tensor work (the binding pipe).
// mode 0: C = A@W^T (+bias +resid), scatter rows.
// mode 1: up+SwiGLU fused (interleaved h/gate B-row gather, gelu in epilogue).
#define TM 128
#define TN 256
#define BK 32
#define NSTAGE 3
#define LDS_STRIDE 40
#define A_TILE_F (128 * LDS_STRIDE)
#define B_TILE_F (256 * LDS_STRIDE)
#define STAGE_F  (A_TILE_F + B_TILE_F)
#define GEMM_SMEM (NSTAGE * STAGE_F * 4)   // 184,320 B

__global__ __launch_bounds__(256, 1)
void gemm_tc_kernel(const float* __restrict__ Aext,
                    const float* __restrict__ Bw,
                    const float* __restrict__ bias,
                    const float* __restrict__ resid,
                    int a_sel, int out_sel, int mode,
                    int Kdim, int Nt, int row_shift) {
    extern __shared__ float sm[];
    const float* A   = (a_sel == 0) ? Aext : (a_sel == 1 ? g_h1 : g_h2);
    float*       Out = (out_sel == 1) ? g_h1 : (out_sel == 2 ? g_h2 : g_logits);

    int e   = blockIdx.z;
    int cnt = g_cnt[e];
    int m0  = blockIdx.y * TM;
    if (m0 >= cnt) return;
    int n0  = blockIdx.x * TN;
    int mrem = cnt - m0;                 // valid rows in this m-tile (1..TM)

    const float* Bexp = Bw + (size_t)e * Nt * Kdim;
    const int*   rows = g_rows[e];
    int tid = threadIdx.x, wid = tid >> 5, lane = tid & 31;

    const bool f4 = ((Kdim & 3) == 0);
    const int  nch = (Kdim + BK - 1) / BK;

    auto brow_ptr = [&](int gn, bool& ok) -> const float* {
        if (mode == 1) {
            int f = gn >> 1;
            ok = (f < DFF_);
            size_t r = (gn & 1) ? (size_t)(DFF_ + f) : (size_t)f;
            return Bexp + r * Kdim;
        }
        ok = (gn < Nt);
        return Bexp + (size_t)gn * Kdim;
    };

    auto load_tile = [&](int i, int s) {
        int k0 = i * BK;
        float* Ab = sm + s * STAGE_F;
        float* Bb = Ab + A_TILE_F;
        uint32_t Au = smem_u32(Ab), Bu = smem_u32(Bb);
        if (f4) {
            for (int u = tid; u < 128 * 8; u += 256) {
                int r = u >> 3, c = u & 7, kg = k0 + c * 4;
                int gm = m0 + r;
                uint32_t dA = Au + (uint32_t)(r * LDS_STRIDE + c * 4) * 4u;
                if (gm < cnt) {
                    int pr = rows[gm];
                    int rr = row_shift ? (pr >> 1) : pr;
                    CPA16(dA, A + (size_t)rr * Kdim + kg);
                } else {
                    *(float4*)(Ab + r * LDS_STRIDE + c * 4) = make_float4(0, 0, 0, 0);
                }
            }
            for (int u = tid; u < 256 * 8; u += 256) {
                int r = u >> 3, c = u & 7, kg = k0 + c * 4;
                bool ok; const float* src = brow_ptr(n0 + r, ok);
                uint32_t dB = Bu + (uint32_t)(r * LDS_STRIDE + c * 4) * 4u;
                if (ok) CPA16(dB, src + kg);
                else    *(float4*)(Bb + r * LDS_STRIDE + c * 4) = make_float4(0, 0, 0, 0);
            }
        } else {
            for (int u = tid; u < 128 * 16; u += 256) {
                int r = u >> 4, c = u & 15, kg = k0 + c * 2;
                int gm = m0 + r;
                uint32_t dA = Au + (uint32_t)(r * LDS_STRIDE + c * 2) * 4u;
                if (gm < cnt && kg < Kdim) {
                    int pr = rows[gm];
                    int rr = row_shift ? (pr >> 1) : pr;
                    CPA8(dA, A + (size_t)rr * Kdim + kg);
                } else {
                    *(float2*)(Ab + r * LDS_STRIDE + c * 2) = make_float2(0, 0);
                }
            }
            for (int u = tid; u < 256 * 16; u += 256) {
                int r = u >> 4, c = u & 15, kg = k0 + c * 2;
                bool ok; const float* src = brow_ptr(n0 + r, ok);
                uint32_t dB = Bu + (uint32_t)(r * LDS_STRIDE + c * 2) * 4u;
                if (ok && kg < Kdim) CPA8(dB, src + kg);
                else *(float2*)(Bb + r * LDS_STRIDE + c * 2) = make_float2(0, 0);
            }
        }
    };

    // warp layout: 2 (m) x 4 (n); warp tile 64 x 64
    int wy = wid >> 2, wx = wid & 3;
    int mw = wy * 64, nw = wx * 64;
    int lr = lane >> 2, lc = lane & 3;

    // which m-subtiles (16 rows each) of this warp are live
    bool mlive[4];
#pragma unroll
    for (int mt = 0; mt < 4; mt++) mlive[mt] = (mw + mt * 16) < mrem;

    float acc[4][8][4];
#pragma unroll
    for (int i = 0; i < 4; i++)
#pragma unroll
        for (int j = 0; j < 8; j++)
#pragma unroll
            for (int q = 0; q < 4; q++) acc[i][j][q] = 0.f;

    load_tile(0, 0);
    CPA_COMMIT();
    if (nch > 1) load_tile(1, 1);
    CPA_COMMIT();

    for (int it = 0; it < nch; it++) {
        CPA_WAIT(1);
        __syncthreads();

        if (it + 2 < nch) load_tile(it + 2, (it + 2) % NSTAGE);
        CPA_COMMIT();

        const float* As = sm + (it % NSTAGE) * STAGE_F;
        const float* Bs = As + A_TILE_F;
#pragma unroll
        for (int ks = 0; ks < BK; ks += 16) {
            uint32_t af[4][4], bf[8][2];
#pragma unroll
            for (int nt = 0; nt < 8; nt++) {
                const float* q = Bs + (nw + nt * 8 + lr) * LDS_STRIDE + ks + 2 * lc;
                float2 u0 = *(const float2*)(q);
                float2 u1 = *(const float2*)(q + 8);
                bf[nt][0] = packbf(u0.x, u0.y);
                bf[nt][1] = packbf(u1.x, u1.y);
            }
#pragma unroll
            for (int mt = 0; mt < 4; mt++) {
                if (!mlive[mt]) continue;          // warp-uniform skip
                const float* p = As + (mw + mt * 16 + lr) * LDS_STRIDE + ks + 2 * lc;
                float2 v0 = *(const float2*)(p);
                float2 v1 = *(const float2*)(p + 8 * LDS_STRIDE);
                float2 v2 = *(const float2*)(p + 8);
                float2 v3 = *(const float2*)(p + 8 * LDS_STRIDE + 8);
                af[mt][0] = packbf(v0.x, v0.y);
                af[mt][1] = packbf(v1.x, v1.y);
                af[mt][2] = packbf(v2.x, v2.y);
                af[mt][3] = packbf(v3.x, v3.y);
#pragma unroll
                for (int nt = 0; nt < 8; nt++)
                    mma_bf16(acc[mt][nt], af[mt], bf[nt]);
            }
        }
    }

    __syncthreads();

    // ---- epilogue ----
    if (mode == 1) {
        const float* bb = bias + (size_t)e * DFF2_;
#pragma unroll
        for (int mt = 0; mt < 4; mt++) {
            if (!mlive[mt]) continue;
#pragma unroll
            for (int half = 0; half < 2; half++) {
                int rg = m0 + mw + mt * 16 + lr + half * 8;
                if (rg >= cnt) continue;
                int pair = rows[rg];
                size_t obase = (size_t)pair * DFF_;
#pragma unroll
                for (int nt = 0; nt < 8; nt++) {
                    int cg = n0 + nw + nt * 8 + 2 * lc;   // even col
                    int f  = cg >> 1;
                    if (f >= DFF_) continue;
                    float h = acc[mt][nt][half * 2 + 0] + bb[f];
                    float g = acc[mt][nt][half * 2 + 1] + bb[DFF_ + f];
                    float ge = 0.5f * g * (1.f + erff(g * 0.70710678118654752440f));
                    Out[obase + f] = h * ge;
                }
            }
        }
    } else {
        const float* bb = bias ? bias + (size_t)e * Nt : nullptr;
#pragma unroll
        for (int mt = 0; mt < 4; mt++) {
            if (!mlive[mt]) continue;
#pragma unroll
            for (int half = 0; half < 2; half++) {
                int rg = m0 + mw + mt * 16 + lr + half * 8;
                if (rg >= cnt) continue;
                int pair = rows[rg];
                size_t obase = (size_t)pair * Nt;
                const float* rr = resid ? resid + (size_t)(pair >> 1) * Nt : nullptr;
#pragma unroll
                for (int nt = 0; nt < 8; nt++) {
                    int cg = n0 + nw + nt * 8 + 2 * lc;
#pragma unroll
                    for (int q = 0; q < 2; q++) {
                        int col = cg + q;
                        if (col >= Nt) continue;
                        float v = acc[mt][nt][half * 2 + q];
                        if (bb) v += bb[col];
                        if (rr) v += rr[col];
                        Out[obase + col] = v;
                    }
                }
            }
        }
    }
}

// ------------------------- online logsumexp over vocab (single pass) ---------
__global__ void lse_kernel() {
    int p = blockIdx.x;
    const float* l = g_logits + (size_t)p * VOCAB_;
    int tid = threadIdx.x;
    float m = -INFINITY, s = 0.f;
    for (int v = tid; v < VOCAB_; v += 256) {
        float xv = l[v];
        if (xv > m) { s = s * expf(m - xv) + 1.f; m = xv; }
        else        { s += expf(xv - m); }
    }
    __shared__ float rm[256], rs[256];
    rm[tid] = m; rs[tid] = s;
    __syncthreads();
    for (int st = 128; st > 0; st >>= 1) {
        if (tid < st) {
            float m2 = rm[tid + st], s2 = rs[tid + st];
            float mm = fmaxf(rm[tid], m2);
            rs[tid] = rs[tid] * expf(rm[tid] - mm) + s2 * expf(m2 - mm);
            rm[tid] = mm;
        }
        __syncthreads();
    }
    if (tid == 0) g_lse[p] = rm[0] + logf(rs[0]);
}

// ------------------------- combine two experts per token ---------------------
__global__ void combine_kernel(float* __restrict__ out) {
    size_t idx = (size_t)blockIdx.x * blockDim.x + threadIdx.x;
    const size_t total = (size_t)S_ * VOCAB_;
    if (idx >= total) return;
    int s = (int)(idx / VOCAB_);
    int v = (int)(idx % VOCAB_);
    int p0 = 2 * s, p1 = 2 * s + 1;
    float a0 = g_logits[(size_t)p0 * VOCAB_ + v] + g_gate[p0] - g_lse[p0];
    float a1 = g_logits[(size_t)p1 * VOCAB_ + v] + g_gate[p1] - g_lse[p1];
    float m = fmaxf(a0, a1);
    out[idx] = m + logf(expf(a0 - m) + expf(a1 - m));
}

// ------------------------- launch -------------------------
extern "C" void kernel_launch(void* const* d_in, const int* in_sizes, int n_in,
                              void* d_out, int out_size) {
    const float *x = nullptr, *Wr = nullptr, *Wup = nullptr,
                *bup = nullptr, *Wdown = nullptr, *Wproj = nullptr;
    for (int i = 0; i < n_in; i++) {
        const float* p = (const float*)d_in[i];
        switch (in_sizes[i]) {
            case S_ * DIM_:            x     = p; break;
            case E_ * DIM_:            Wr    = p; break;
            case E_ * DFF2_ * DIM_:    Wup   = p; break;
            case E_ * DFF2_:           bup   = p; break;
            case E_ * DIM_ * DFF_:     Wdown = p; break;
            case E_ * VOCAB_ * DIM_:   Wproj = p; break;
        }
    }
    if (!x)     x     = (const float*)d_in[0];
    if (!Wr)    Wr    = (const float*)d_in[1];
    if (!Wup)   Wup   = (const float*)d_in[2];
    if (!bup)   bup   = (const float*)d_in[3];
    if (!Wdown) Wdown = (const float*)d_in[4];
    if (!Wproj) Wproj = (const float*)d_in[5];
    float* out = (float*)d_out;

    cudaFuncSetAttribute(gemm_tc_kernel,
                         cudaFuncAttributeMaxDynamicSharedMemorySize, GEMM_SMEM);

    // 1) router + fused grouping
    router_kernel<<<S_, 256>>>(x, Wr);

    // 2) up + fused SwiGLU: g_h1 = h * gelu(gate)
    {
        dim3 grid((DFF2_ + TN - 1) / TN, (NPAIR + TM - 1) / TM, E_);
        gemm_tc_kernel<<<grid, 256, GEMM_SMEM>>>(x, Wup, bup, nullptr,
                                                 0, 1, 1, DIM_, DFF2_, 1);
    }
    // 3) down + residual: g_h2 = g_h1 @ Wdown[e]^T + x
    {
        dim3 grid((DIM_ + TN - 1) / TN, (NPAIR + TM - 1) / TM, E_);
        gemm_tc_kernel<<<grid, 256, GEMM_SMEM>>>(nullptr, Wdown, nullptr, x,
                                                 1, 2, 0, DFF_, DIM_, 0);
    }
    // 4) proj: g_logits = g_h2 @ Wproj[e]^T   <-- ncu capture slot (#4)
    {
        dim3 grid((VOCAB_ + TN - 1) / TN, (NPAIR + TM - 1) / TM, E_);
        gemm_tc_kernel<<<grid, 256, GEMM_SMEM>>>(nullptr, Wproj, nullptr, nullptr,
                                                 2, 3, 0, DIM_, VOCAB_, 0);
    }
    // 5) per-pair LSE, 6) combine
    lse_kernel<<<NPAIR, 256>>>();
    {
        size_t total = (size_t)S_ * VOCAB_;
        combine_kernel<<<(int)((total + 255) / 256), 256>>>(out);
    }
}

// round 15
// speedup vs baseline: 1.2432x; 1.0357x over previous
#include <cuda_runtime.h>
#include <cuda_bf16.h>
#include <math.h>
#include <stdint.h>

// Problem constants
#define E_      8
#define S_      512
#define DIM_    1024
#define DFF_    2730
#define DFF2_   5460
#define VOCAB_  32000
#define NPAIR   1024   // S_ * 2

// ------------------------- device scratch (device-code access only) ----------
__device__ int   g_done;
__device__ int   g_cnt[E_];
__device__ int   g_rows[E_][NPAIR];
__device__ int   g_eid[NPAIR];
__device__ float g_gate[NPAIR];
__device__ float g_lse[NPAIR];
__device__ float g_h1[(size_t)NPAIR * DFF_];
__device__ float g_h2[(size_t)NPAIR * DIM_];
__device__ float g_logits[(size_t)NPAIR * VOCAB_];

// ------------------------- PTX helpers (sm_80-era, plain sm_103-safe) --------
__device__ __forceinline__ uint32_t smem_u32(const void* p) {
    uint32_t a;
    asm("{ .reg .u64 t; cvta.to.shared.u64 t, %1; cvt.u32.u64 %0, t; }"
        : "=r"(a) : "l"(p));
    return a;
}
#define CPA16(dst, src) \
    asm volatile("cp.async.cg.shared.global [%0], [%1], 16;" :: "r"(dst), "l"(src))
#define CPA8(dst, src) \
    asm volatile("cp.async.ca.shared.global [%0], [%1], 8;" :: "r"(dst), "l"(src))
#define CPA_COMMIT() asm volatile("cp.async.commit_group;" ::: "memory")
#define CPA_WAIT(n)  asm volatile("cp.async.wait_group %0;" :: "n"(n) : "memory")

__device__ __forceinline__ uint32_t packbf(float lo, float hi) {
    uint32_t r;
    asm("cvt.rn.bf16x2.f32 %0, %1, %2;" : "=r"(r) : "f"(hi), "f"(lo));
    return r;
}
__device__ __forceinline__ void mma_bf16(float* d, const uint32_t* a, const uint32_t* b) {
    asm volatile(
        "mma.sync.aligned.m16n8k16.row.col.f32.bf16.bf16.f32 "
        "{%0,%1,%2,%3}, {%4,%5,%6,%7}, {%8,%9}, {%0,%1,%2,%3};"
        : "+f"(d[0]), "+f"(d[1]), "+f"(d[2]), "+f"(d[3])
        : "r"(a[0]), "r"(a[1]), "r"(a[2]), "r"(a[3]), "r"(b[0]), "r"(b[1]));
}

// ------------------------- router + fused grouping -------------------------
__global__ void router_kernel(const float* __restrict__ x,
                              const float* __restrict__ Wr) {
    int s = blockIdx.x;
    const float* xr = x + (size_t)s * DIM_;
    float acc[E_];
#pragma unroll
    for (int e = 0; e < E_; e++) acc[e] = 0.f;
    for (int d = threadIdx.x; d < DIM_; d += blockDim.x) {
        float xv = xr[d];
#pragma unroll
        for (int e = 0; e < E_; e++) acc[e] = fmaf(xv, Wr[e * DIM_ + d], acc[e]);
    }
    __shared__ float red[256];
    __shared__ float score[E_];
#pragma unroll
    for (int e = 0; e < E_; e++) {
        red[threadIdx.x] = acc[e];
        __syncthreads();
        for (int st = 128; st > 0; st >>= 1) {
            if (threadIdx.x < st) red[threadIdx.x] += red[threadIdx.x + st];
            __syncthreads();
        }
        if (threadIdx.x == 0) score[e] = red[0];
        __syncthreads();
    }
    if (threadIdx.x == 0) {
        int i0 = 0; float s0 = score[0];
        for (int e = 1; e < E_; e++) if (score[e] > s0) { s0 = score[e]; i0 = e; }
        int i1 = -1; float s1 = -INFINITY;
        for (int e = 0; e < E_; e++) {
            if (e == i0) continue;
            if (score[e] > s1) { s1 = score[e]; i1 = e; }
        }
        float m   = fmaxf(s0, s1);
        float lse = m + logf(expf(s0 - m) + expf(s1 - m));
        int p0 = 2 * s, p1 = 2 * s + 1;
        g_gate[p0] = s0 - lse;  g_gate[p1] = s1 - lse;
        g_eid[p0]  = i0;        g_eid[p1]  = i1;
    }

    __shared__ int amLast;
    __threadfence();
    if (threadIdx.x == 0) {
        int t = atomicAdd(&g_done, 1);
        amLast = (t == S_ - 1) ? 1 : 0;
    }
    __syncthreads();
    if (amLast) {
        __threadfence();
        int w = threadIdx.x / 32, lane = threadIdx.x % 32;
        if (w < E_) {
            int count = 0;
            for (int base = 0; base < NPAIR; base += 32) {
                int p  = base + lane;
                int id = g_eid[p];
                unsigned mask = __ballot_sync(0xffffffffu, id == w);
                if (id == w)
                    g_rows[w][count + __popc(mask & ((1u << lane) - 1u))] = p;
                count += __popc(mask);
            }
            if (lane == 0) g_cnt[w] = count;
        }
        if (threadIdx.x == 0) g_done = 0;
        __threadfence();
    }
}

// ------------------------- bf16 mma.sync grouped GEMM, 3-stage ring ----------
// Block tile 128x256, BK=32, 512 threads = 16 warps (2m x 8n), warp tile 64x32.
// Occupancy experiment: 4 warps/SMSP (was 2) to cover LDS->CVT->HMMA latency.
// m-subtile skipping removes padded-M tensor work.
// mode 0: C = A@W^T (+bias +resid), scatter rows.
// mode 1: up+SwiGLU fused (interleaved h/gate B-row gather, gelu in epilogue).
#define TM 128
#define TN 256
#define BK 32
#define NTHREADS 512
#define NSTAGE 3
#define LDS_STRIDE 40
#define A_TILE_F (128 * LDS_STRIDE)
#define B_TILE_F (256 * LDS_STRIDE)
#define STAGE_F  (A_TILE_F + B_TILE_F)
#define GEMM_SMEM (NSTAGE * STAGE_F * 4)   // 184,320 B

__global__ __launch_bounds__(NTHREADS, 1)
void gemm_tc_kernel(const float* __restrict__ Aext,
                    const float* __restrict__ Bw,
                    const float* __restrict__ bias,
                    const float* __restrict__ resid,
                    int a_sel, int out_sel, int mode,
                    int Kdim, int Nt, int row_shift) {
    extern __shared__ float sm[];
    const float* A   = (a_sel == 0) ? Aext : (a_sel == 1 ? g_h1 : g_h2);
    float*       Out = (out_sel == 1) ? g_h1 : (out_sel == 2 ? g_h2 : g_logits);

    int e   = blockIdx.z;
    int cnt = g_cnt[e];
    int m0  = blockIdx.y * TM;
    if (m0 >= cnt) return;
    int n0  = blockIdx.x * TN;
    int mrem = cnt - m0;                 // valid rows in this m-tile (1..TM)

    const float* Bexp = Bw + (size_t)e * Nt * Kdim;
    const int*   rows = g_rows[e];
    int tid = threadIdx.x, wid = tid >> 5, lane = tid & 31;

    const bool f4 = ((Kdim & 3) == 0);
    const int  nch = (Kdim + BK - 1) / BK;

    auto brow_ptr = [&](int gn, bool& ok) -> const float* {
        if (mode == 1) {
            int f = gn >> 1;
            ok = (f < DFF_);
            size_t r = (gn & 1) ? (size_t)(DFF_ + f) : (size_t)f;
            return Bexp + r * Kdim;
        }
        ok = (gn < Nt);
        return Bexp + (size_t)gn * Kdim;
    };

    auto load_tile = [&](int i, int s) {
        int k0 = i * BK;
        float* Ab = sm + s * STAGE_F;
        float* Bb = Ab + A_TILE_F;
        uint32_t Au = smem_u32(Ab), Bu = smem_u32(Bb);
        if (f4) {
            for (int u = tid; u < 128 * 8; u += NTHREADS) {
                int r = u >> 3, c = u & 7, kg = k0 + c * 4;
                int gm = m0 + r;
                uint32_t dA = Au + (uint32_t)(r * LDS_STRIDE + c * 4) * 4u;
                if (gm < cnt) {
                    int pr = rows[gm];
                    int rr = row_shift ? (pr >> 1) : pr;
                    CPA16(dA, A + (size_t)rr * Kdim + kg);
                } else {
                    *(float4*)(Ab + r * LDS_STRIDE + c * 4) = make_float4(0, 0, 0, 0);
                }
            }
            for (int u = tid; u < 256 * 8; u += NTHREADS) {
                int r = u >> 3, c = u & 7, kg = k0 + c * 4;
                bool ok; const float* src = brow_ptr(n0 + r, ok);
                uint32_t dB = Bu + (uint32_t)(r * LDS_STRIDE + c * 4) * 4u;
                if (ok) CPA16(dB, src + kg);
                else    *(float4*)(Bb + r * LDS_STRIDE + c * 4) = make_float4(0, 0, 0, 0);
            }
        } else {
            for (int u = tid; u < 128 * 16; u += NTHREADS) {
                int r = u >> 4, c = u & 15, kg = k0 + c * 2;
                int gm = m0 + r;
                uint32_t dA = Au + (uint32_t)(r * LDS_STRIDE + c * 2) * 4u;
                if (gm < cnt && kg < Kdim) {
                    int pr = rows[gm];
                    int rr = row_shift ? (pr >> 1) : pr;
                    CPA8(dA, A + (size_t)rr * Kdim + kg);
                } else {
                    *(float2*)(Ab + r * LDS_STRIDE + c * 2) = make_float2(0, 0);
                }
            }
            for (int u = tid; u < 256 * 16; u += NTHREADS) {
                int r = u >> 4, c = u & 15, kg = k0 + c * 2;
                bool ok; const float* src = brow_ptr(n0 + r, ok);
                uint32_t dB = Bu + (uint32_t)(r * LDS_STRIDE + c * 2) * 4u;
                if (ok && kg < Kdim) CPA8(dB, src + kg);
                else *(float2*)(Bb + r * LDS_STRIDE + c * 2) = make_float2(0, 0);
            }
        }
    };

    // warp layout: 2 (m) x 8 (n); warp tile 64 x 32
    int wy = wid >> 3, wx = wid & 7;
    int mw = wy * 64, nw = wx * 32;
    int lr = lane >> 2, lc = lane & 3;

    // which m-subtiles (16 rows each) of this warp are live
    bool mlive[4];
#pragma unroll
    for (int mt = 0; mt < 4; mt++) mlive[mt] = (mw + mt * 16) < mrem;

    float acc[4][4][4];
#pragma unroll
    for (int i = 0; i < 4; i++)
#pragma unroll
        for (int j = 0; j < 4; j++)
#pragma unroll
            for (int q = 0; q < 4; q++) acc[i][j][q] = 0.f;

    load_tile(0, 0);
    CPA_COMMIT();
    if (nch > 1) load_tile(1, 1);
    CPA_COMMIT();

    for (int it = 0; it < nch; it++) {
        CPA_WAIT(1);
        __syncthreads();

        if (it + 2 < nch) load_tile(it + 2, (it + 2) % NSTAGE);
        CPA_COMMIT();

        const float* As = sm + (it % NSTAGE) * STAGE_F;
        const float* Bs = As + A_TILE_F;
#pragma unroll
        for (int ks = 0; ks < BK; ks += 16) {
            uint32_t af[4][4], bf[4][2];
#pragma unroll
            for (int nt = 0; nt < 4; nt++) {
                const float* q = Bs + (nw + nt * 8 + lr) * LDS_STRIDE + ks + 2 * lc;
                float2 u0 = *(const float2*)(q);
                float2 u1 = *(const float2*)(q + 8);
                bf[nt][0] = packbf(u0.x, u0.y);
                bf[nt][1] = packbf(u1.x, u1.y);
            }
#pragma unroll
            for (int mt = 0; mt < 4; mt++) {
                if (!mlive[mt]) continue;          // warp-uniform skip
                const float* p = As + (mw + mt * 16 + lr) * LDS_STRIDE + ks + 2 * lc;
                float2 v0 = *(const float2*)(p);
                float2 v1 = *(const float2*)(p + 8 * LDS_STRIDE);
                float2 v2 = *(const float2*)(p + 8);
                float2 v3 = *(const float2*)(p + 8 * LDS_STRIDE + 8);
                af[mt][0] = packbf(v0.x, v0.y);
                af[mt][1] = packbf(v1.x, v1.y);
                af[mt][2] = packbf(v2.x, v2.y);
                af[mt][3] = packbf(v3.x, v3.y);
#pragma unroll
                for (int nt = 0; nt < 4; nt++)
                    mma_bf16(acc[mt][nt], af[mt], bf[nt]);
            }
        }
    }

    __syncthreads();

    // ---- epilogue ----
    if (mode == 1) {
        const float* bb = bias + (size_t)e * DFF2_;
#pragma unroll
        for (int mt = 0; mt < 4; mt++) {
            if (!mlive[mt]) continue;
#pragma unroll
            for (int half = 0; half < 2; half++) {
                int rg = m0 + mw + mt * 16 + lr + half * 8;
                if (rg >= cnt) continue;
                int pair = rows[rg];
                size_t obase = (size_t)pair * DFF_;
#pragma unroll
                for (int nt = 0; nt < 4; nt++) {
                    int cg = n0 + nw + nt * 8 + 2 * lc;   // even col
                    int f  = cg >> 1;
                    if (f >= DFF_) continue;
                    float h = acc[mt][nt][half * 2 + 0] + bb[f];
                    float g = acc[mt][nt][half * 2 + 1] + bb[DFF_ + f];
                    float ge = 0.5f * g * (1.f + erff(g * 0.70710678118654752440f));
                    Out[obase + f] = h * ge;
                }
            }
        }
    } else {
        const float* bb = bias ? bias + (size_t)e * Nt : nullptr;
#pragma unroll
        for (int mt = 0; mt < 4; mt++) {
            if (!mlive[mt]) continue;
#pragma unroll
            for (int half = 0; half < 2; half++) {
                int rg = m0 + mw + mt * 16 + lr + half * 8;
                if (rg >= cnt) continue;
                int pair = rows[rg];
                size_t obase = (size_t)pair * Nt;
                const float* rr = resid ? resid + (size_t)(pair >> 1) * Nt : nullptr;
#pragma unroll
                for (int nt = 0; nt < 4; nt++) {
                    int cg = n0 + nw + nt * 8 + 2 * lc;
#pragma unroll
                    for (int q = 0; q < 2; q++) {
                        int col = cg + q;
                        if (col >= Nt) continue;
                        float v = acc[mt][nt][half * 2 + q];
                        if (bb) v += bb[col];
                        if (rr) v += rr[col];
                        Out[obase + col] = v;
                    }
                }
            }
        }
    }
}

// ------------------------- online logsumexp over vocab (single pass) ---------
__global__ void lse_kernel() {
    int p = blockIdx.x;
    const float* l = g_logits + (size_t)p * VOCAB_;
    int tid = threadIdx.x;
    float m = -INFINITY, s = 0.f;
    for (int v = tid; v < VOCAB_; v += 256) {
        float xv = l[v];
        if (xv > m) { s = s * expf(m - xv) + 1.f; m = xv; }
        else        { s += expf(xv - m); }
    }
    __shared__ float rm[256], rs[256];
    rm[tid] = m; rs[tid] = s;
    __syncthreads();
    for (int st = 128; st > 0; st >>= 1) {
        if (tid < st) {
            float m2 = rm[tid + st], s2 = rs[tid + st];
            float mm = fmaxf(rm[tid], m2);
            rs[tid] = rs[tid] * expf(rm[tid] - mm) + s2 * expf(m2 - mm);
            rm[tid] = mm;
        }
        __syncthreads();
    }
    if (tid == 0) g_lse[p] = rm[0] + logf(rs[0]);
}

// ------------------------- combine two experts per token ---------------------
__global__ void combine_kernel(float* __restrict__ out) {
    size_t idx = (size_t)blockIdx.x * blockDim.x + threadIdx.x;
    const size_t total = (size_t)S_ * VOCAB_;
    if (idx >= total) return;
    int s = (int)(idx / VOCAB_);
    int v = (int)(idx % VOCAB_);
    int p0 = 2 * s, p1 = 2 * s + 1;
    float a0 = g_logits[(size_t)p0 * VOCAB_ + v] + g_gate[p0] - g_lse[p0];
    float a1 = g_logits[(size_t)p1 * VOCAB_ + v] + g_gate[p1] - g_lse[p1];
    float m = fmaxf(a0, a1);
    out[idx] = m + logf(expf(a0 - m) + expf(a1 - m));
}

// ------------------------- launch -------------------------
extern "C" void kernel_launch(void* const* d_in, const int* in_sizes, int n_in,
                              void* d_out, int out_size) {
    const float *x = nullptr, *Wr = nullptr, *Wup = nullptr,
                *bup = nullptr, *Wdown = nullptr, *Wproj = nullptr;
    for (int i = 0; i < n_in; i++) {
        const float* p = (const float*)d_in[i];
        switch (in_sizes[i]) {
            case S_ * DIM_:            x     = p; break;
            case E_ * DIM_:            Wr    = p; break;
            case E_ * DFF2_ * DIM_:    Wup   = p; break;
            case E_ * DFF2_:           bup   = p; break;
            case E_ * DIM_ * DFF_:     Wdown = p; break;
            case E_ * VOCAB_ * DIM_:   Wproj = p; break;
        }
    }
    if (!x)     x     = (const float*)d_in[0];
    if (!Wr)    Wr    = (const float*)d_in[1];
    if (!Wup)   Wup   = (const float*)d_in[2];
    if (!bup)   bup   = (const float*)d_in[3];
    if (!Wdown) Wdown = (const float*)d_in[4];
    if (!Wproj) Wproj = (const float*)d_in[5];
    float* out = (float*)d_out;

    cudaFuncSetAttribute(gemm_tc_kernel,
                         cudaFuncAttributeMaxDynamicSharedMemorySize, GEMM_SMEM);

    // 1) router + fused grouping
    router_kernel<<<S_, 256>>>(x, Wr);

    // 2) up + fused SwiGLU: g_h1 = h * gelu(gate)
    {
        dim3 grid((DFF2_ + TN - 1) / TN, (NPAIR + TM - 1) / TM, E_);
        gemm_tc_kernel<<<grid, NTHREADS, GEMM_SMEM>>>(x, Wup, bup, nullptr,
                                                      0, 1, 1, DIM_, DFF2_, 1);
    }
    // 3) down + residual: g_h2 = g_h1 @ Wdown[e]^T + x
    {
        dim3 grid((DIM_ + TN - 1) / TN, (NPAIR + TM - 1) / TM, E_);
        gemm_tc_kernel<<<grid, NTHREADS, GEMM_SMEM>>>(nullptr, Wdown, nullptr, x,
                                                      1, 2, 0, DFF_, DIM_, 0);
    }
    // 4) proj: g_logits = g_h2 @ Wproj[e]^T   <-- ncu capture slot (#4)
    {
        dim3 grid((VOCAB_ + TN - 1) / TN, (NPAIR + TM - 1) / TM, E_);
        gemm_tc_kernel<<<grid, NTHREADS, GEMM_SMEM>>>(nullptr, Wproj, nullptr, nullptr,
                                                      2, 3, 0, DIM_, VOCAB_, 0);
    }
    // 5) per-pair LSE, 6) combine
    lse_kernel<<<NPAIR, 256>>>();
    {
        size_t total = (size_t)S_ * VOCAB_;
        combine_kernel<<<(int)((total + 255) / 256), 256>>>(out);
    }
}

// round 16
// speedup vs baseline: 1.3260x; 1.0666x over previous
#include <cuda_runtime.h>
#include <cuda_bf16.h>
#include <math.h>
#include <stdint.h>

// Problem constants
#define E_      8
#define S_      512
#define DIM_    1024
#define DFF_    2730
#define DFF2_   5460
#define VOCAB_  32000
#define NPAIR   1024   // S_ * 2

// ------------------------- device scratch (device-code access only) ----------
__device__ int   g_done;
__device__ int   g_cnt[E_];
__device__ int   g_rows[E_][NPAIR];
__device__ int   g_eid[NPAIR];
__device__ float g_gate[NPAIR];
__device__ float g_lse[NPAIR];
__device__ float g_h1[(size_t)NPAIR * DFF_];
__device__ float g_h2[(size_t)NPAIR * DIM_];
__device__ float g_logits[(size_t)NPAIR * VOCAB_];

// ------------------------- PTX helpers (sm_75/80-era, plain sm_103-safe) -----
__device__ __forceinline__ uint32_t smem_u32(const void* p) {
    uint32_t a;
    asm("{ .reg .u64 t; cvta.to.shared.u64 t, %1; cvt.u32.u64 %0, t; }"
        : "=r"(a) : "l"(p));
    return a;
}
__device__ __forceinline__ uint32_t packbf(float lo, float hi) {
    uint32_t r;
    asm("cvt.rn.bf16x2.f32 %0, %1, %2;" : "=r"(r) : "f"(hi), "f"(lo));
    return r;
}
#define STS64(addr, r0, r1) \
    asm volatile("st.shared.v2.b32 [%0], {%1,%2};" :: "r"(addr), "r"(r0), "r"(r1) : "memory")
#define STS32(addr, r0) \
    asm volatile("st.shared.b32 [%0], %1;" :: "r"(addr), "r"(r0) : "memory")
#define LDSM_X4(r0, r1, r2, r3, addr) \
    asm volatile("ldmatrix.sync.aligned.m8n8.x4.shared.b16 {%0,%1,%2,%3}, [%4];" \
        : "=r"(r0), "=r"(r1), "=r"(r2), "=r"(r3) : "r"(addr))

__device__ __forceinline__ void mma_bf16(float* d, const uint32_t* a, const uint32_t* b) {
    asm volatile(
        "mma.sync.aligned.m16n8k16.row.col.f32.bf16.bf16.f32 "
        "{%0,%1,%2,%3}, {%4,%5,%6,%7}, {%8,%9}, {%0,%1,%2,%3};"
        : "+f"(d[0]), "+f"(d[1]), "+f"(d[2]), "+f"(d[3])
        : "r"(a[0]), "r"(a[1]), "r"(a[2]), "r"(a[3]), "r"(b[0]), "r"(b[1]));
}

// ------------------------- router + fused grouping -------------------------
__global__ void router_kernel(const float* __restrict__ x,
                              const float* __restrict__ Wr) {
    int s = blockIdx.x;
    const float* xr = x + (size_t)s * DIM_;
    float acc[E_];
#pragma unroll
    for (int e = 0; e < E_; e++) acc[e] = 0.f;
    for (int d = threadIdx.x; d < DIM_; d += blockDim.x) {
        float xv = xr[d];
#pragma unroll
        for (int e = 0; e < E_; e++) acc[e] = fmaf(xv, Wr[e * DIM_ + d], acc[e]);
    }
    __shared__ float red[256];
    __shared__ float score[E_];
#pragma unroll
    for (int e = 0; e < E_; e++) {
        red[threadIdx.x] = acc[e];
        __syncthreads();
        for (int st = 128; st > 0; st >>= 1) {
            if (threadIdx.x < st) red[threadIdx.x] += red[threadIdx.x + st];
            __syncthreads();
        }
        if (threadIdx.x == 0) score[e] = red[0];
        __syncthreads();
    }
    if (threadIdx.x == 0) {
        int i0 = 0; float s0 = score[0];
        for (int e = 1; e < E_; e++) if (score[e] > s0) { s0 = score[e]; i0 = e; }
        int i1 = -1; float s1 = -INFINITY;
        for (int e = 0; e < E_; e++) {
            if (e == i0) continue;
            if (score[e] > s1) { s1 = score[e]; i1 = e; }
        }
        float m   = fmaxf(s0, s1);
        float lse = m + logf(expf(s0 - m) + expf(s1 - m));
        int p0 = 2 * s, p1 = 2 * s + 1;
        g_gate[p0] = s0 - lse;  g_gate[p1] = s1 - lse;
        g_eid[p0]  = i0;        g_eid[p1]  = i1;
    }

    __shared__ int amLast;
    __threadfence();
    if (threadIdx.x == 0) {
        int t = atomicAdd(&g_done, 1);
        amLast = (t == S_ - 1) ? 1 : 0;
    }
    __syncthreads();
    if (amLast) {
        __threadfence();
        int w = threadIdx.x / 32, lane = threadIdx.x % 32;
        if (w < E_) {
            int count = 0;
            for (int base = 0; base < NPAIR; base += 32) {
                int p  = base + lane;
                int id = g_eid[p];
                unsigned mask = __ballot_sync(0xffffffffu, id == w);
                if (id == w)
                    g_rows[w][count + __popc(mask & ((1u << lane) - 1u))] = p;
                count += __popc(mask);
            }
            if (lane == 0) g_cnt[w] = count;
        }
        if (threadIdx.x == 0) g_done = 0;
        __threadfence();
    }
}

// ------------------------- bf16-smem ldmatrix GEMM --------------------------
// Block tile 128x256, BK=32, 512 threads = 16 warps (2m x 8n), warp tile 64x32.
// fp32 LDG -> bf16 pack -> STS; bf16 smem (stride 40 halves, ldmatrix
// conflict-free); fragments via ldmatrix.m8n8.x4. 2-stage smem ring +
// register staging (chunk it+1 in regs while chunk it computes).
// mode 0: C = A@W^T (+bias +resid).  mode 1: up+SwiGLU fused.
#define TM 128
#define TN 256
#define BK 32
#define NTHREADS 512
#define LDH 40                       // halves per row
#define A_H (128 * LDH)              // 5120 halves
#define B_H (256 * LDH)              // 10240 halves
#define A_BYTES (A_H * 2)            // 10240
#define STAGE_BYTES ((A_H + B_H) * 2)  // 30720
#define GEMM_SMEM (2 * STAGE_BYTES)    // 61440

template <bool F4>
__global__ __launch_bounds__(NTHREADS, 1)
void gemm_tc_kernel(const float* __restrict__ Aext,
                    const float* __restrict__ Bw,
                    const float* __restrict__ bias,
                    const float* __restrict__ resid,
                    int a_sel, int out_sel, int mode,
                    int Kdim, int Nt, int row_shift) {
    extern __shared__ char smh[];
    const float* A   = (a_sel == 0) ? Aext : (a_sel == 1 ? g_h1 : g_h2);
    float*       Out = (out_sel == 1) ? g_h1 : (out_sel == 2 ? g_h2 : g_logits);

    int e   = blockIdx.z;
    int cnt = g_cnt[e];
    int m0  = blockIdx.y * TM;
    if (m0 >= cnt) return;
    int n0  = blockIdx.x * TN;
    int mrem = cnt - m0;

    const float* Bexp = Bw + (size_t)e * Nt * Kdim;
    const int*   rows = g_rows[e];
    int tid = threadIdx.x, wid = tid >> 5, lane = tid & 31;
    uint32_t smem_base = smem_u32(smh);

    const int nch = (Kdim + BK - 1) / BK;

    auto brow_ptr = [&](int gn, bool& ok) -> const float* {
        if (mode == 1) {
            int f = gn >> 1;
            ok = (f < DFF_);
            size_t r = (gn & 1) ? (size_t)(DFF_ + f) : (size_t)f;
            return Bexp + r * Kdim;
        }
        ok = (gn < Nt);
        return Bexp + (size_t)gn * Kdim;
    };

    // register staging for one chunk
    float4 ra4[2], rb4[4];
    float2 ra2[4], rb2[8];

    auto ldg_chunk = [&](int i) {
        int k0 = i * BK;
        if constexpr (F4) {
#pragma unroll
            for (int j = 0; j < 2; j++) {            // A: 128r x 8c float4
                int u = tid + j * NTHREADS;
                int r = u >> 3, c = u & 7, kg = k0 + c * 4;
                int gm = m0 + r;
                float4 v = make_float4(0.f, 0.f, 0.f, 0.f);
                if (gm < cnt) {
                    int pr = rows[gm];
                    int rr = row_shift ? (pr >> 1) : pr;
                    v = *(const float4*)(A + (size_t)rr * Kdim + kg);
                }
                ra4[j] = v;
            }
#pragma unroll
            for (int j = 0; j < 4; j++) {            // B: 256r x 8c float4
                int u = tid + j * NTHREADS;
                int r = u >> 3, c = u & 7, kg = k0 + c * 4;
                bool ok; const float* src = brow_ptr(n0 + r, ok);
                float4 v = make_float4(0.f, 0.f, 0.f, 0.f);
                if (ok) v = *(const float4*)(src + kg);
                rb4[j] = v;
            }
        } else {
#pragma unroll
            for (int j = 0; j < 4; j++) {            // A: 128r x 16c float2
                int u = tid + j * NTHREADS;
                int r = u >> 4, c = u & 15, kg = k0 + c * 2;
                int gm = m0 + r;
                float2 v = make_float2(0.f, 0.f);
                if (gm < cnt && kg < Kdim) {
                    int pr = rows[gm];
                    int rr = row_shift ? (pr >> 1) : pr;
                    v = *(const float2*)(A + (size_t)rr * Kdim + kg);
                }
                ra2[j] = v;
            }
#pragma unroll
            for (int j = 0; j < 8; j++) {            // B: 256r x 16c float2
                int u = tid + j * NTHREADS;
                int r = u >> 4, c = u & 15, kg = k0 + c * 2;
                bool ok; const float* src = brow_ptr(n0 + r, ok);
                float2 v = make_float2(0.f, 0.f);
                if (ok && kg < Kdim) v = *(const float2*)(src + kg);
                rb2[j] = v;
            }
        }
    };

    auto sts_chunk = [&](int sbuf) {
        uint32_t base = smem_base + (uint32_t)sbuf * STAGE_BYTES;
        if constexpr (F4) {
#pragma unroll
            for (int j = 0; j < 2; j++) {
                int u = tid + j * NTHREADS;
                int r = u >> 3, c = u & 7;
                uint32_t off = base + (uint32_t)(r * LDH + c * 4) * 2u;
                STS64(off, packbf(ra4[j].x, ra4[j].y), packbf(ra4[j].z, ra4[j].w));
            }
#pragma unroll
            for (int j = 0; j < 4; j++) {
                int u = tid + j * NTHREADS;
                int r = u >> 3, c = u & 7;
                uint32_t off = base + A_BYTES + (uint32_t)(r * LDH + c * 4) * 2u;
                STS64(off, packbf(rb4[j].x, rb4[j].y), packbf(rb4[j].z, rb4[j].w));
            }
        } else {
#pragma unroll
            for (int j = 0; j < 4; j++) {
                int u = tid + j * NTHREADS;
                int r = u >> 4, c = u & 15;
                uint32_t off = base + (uint32_t)(r * LDH + c * 2) * 2u;
                STS32(off, packbf(ra2[j].x, ra2[j].y));
            }
#pragma unroll
            for (int j = 0; j < 8; j++) {
                int u = tid + j * NTHREADS;
                int r = u >> 4, c = u & 15;
                uint32_t off = base + A_BYTES + (uint32_t)(r * LDH + c * 2) * 2u;
                STS32(off, packbf(rb2[j].x, rb2[j].y));
            }
        }
    };

    // warp layout: 2 (m) x 8 (n); warp tile 64 x 32
    int wy = wid >> 3, wx = wid & 7;
    int mw = wy * 64, nw = wx * 32;
    int lr = lane >> 2, lc = lane & 3;

    bool mlive[4];
#pragma unroll
    for (int mt = 0; mt < 4; mt++) mlive[mt] = (mw + mt * 16) < mrem;

    // per-lane ldmatrix row assignment
    int lj = lane >> 3;          // matrix index 0..3
    int lrow = lane & 7;         // row within matrix

    float acc[4][4][4];
#pragma unroll
    for (int i = 0; i < 4; i++)
#pragma unroll
        for (int j = 0; j < 4; j++)
#pragma unroll
            for (int q = 0; q < 4; q++) acc[i][j][q] = 0.f;

    // prologue
    ldg_chunk(0);
    sts_chunk(0);
    __syncthreads();
    if (nch > 1) ldg_chunk(1);

    for (int it = 0; it < nch; it++) {
        uint32_t Au = smem_base + (uint32_t)(it & 1) * STAGE_BYTES;
        uint32_t Bu = Au + A_BYTES;
#pragma unroll
        for (int ks = 0; ks < BK; ks += 16) {
            // B fragments: one x4 per k-half, matrices = nt 0..3
            uint32_t bfr[2][4];
#pragma unroll
            for (int kh = 0; kh < 2; kh++) {
                uint32_t addr = Bu + (uint32_t)((nw + lj * 8 + lrow) * LDH + ks + kh * 8) * 2u;
                LDSM_X4(bfr[kh][0], bfr[kh][1], bfr[kh][2], bfr[kh][3], addr);
            }
#pragma unroll
            for (int mt = 0; mt < 4; mt++) {
                if (!mlive[mt]) continue;
                uint32_t addr = Au + (uint32_t)((mw + mt * 16 + (lj & 1) * 8 + lrow) * LDH
                                                + ks + (lj >> 1) * 8) * 2u;
                uint32_t af[4];
                LDSM_X4(af[0], af[1], af[2], af[3], addr);
#pragma unroll
                for (int nt = 0; nt < 4; nt++) {
                    uint32_t bb[2] = { bfr[0][nt], bfr[1][nt] };
                    mma_bf16(acc[mt][nt], af, bb);
                }
            }
        }
        if (it + 1 < nch) {
            __syncthreads();
            sts_chunk((it + 1) & 1);
            __syncthreads();
            if (it + 2 < nch) ldg_chunk(it + 2);
        }
    }

    __syncthreads();

    // ---- epilogue ----
    if (mode == 1) {
        const float* bb = bias + (size_t)e * DFF2_;
#pragma unroll
        for (int mt = 0; mt < 4; mt++) {
            if (!mlive[mt]) continue;
#pragma unroll
            for (int half = 0; half < 2; half++) {
                int rg = m0 + mw + mt * 16 + lr + half * 8;
                if (rg >= cnt) continue;
                int pair = rows[rg];
                size_t obase = (size_t)pair * DFF_;
#pragma unroll
                for (int nt = 0; nt < 4; nt++) {
                    int cg = n0 + nw + nt * 8 + 2 * lc;   // even col
                    int f  = cg >> 1;
                    if (f >= DFF_) continue;
                    float h = acc[mt][nt][half * 2 + 0] + bb[f];
                    float g = acc[mt][nt][half * 2 + 1] + bb[DFF_ + f];
                    float ge = 0.5f * g * (1.f + erff(g * 0.70710678118654752440f));
                    Out[obase + f] = h * ge;
                }
            }
        }
    } else {
        const float* bb = bias ? bias + (size_t)e * Nt : nullptr;
#pragma unroll
        for (int mt = 0; mt < 4; mt++) {
            if (!mlive[mt]) continue;
#pragma unroll
            for (int half = 0; half < 2; half++) {
                int rg = m0 + mw + mt * 16 + lr + half * 8;
                if (rg >= cnt) continue;
                int pair = rows[rg];
                size_t obase = (size_t)pair * Nt;
                const float* rr = resid ? resid + (size_t)(pair >> 1) * Nt : nullptr;
#pragma unroll
                for (int nt = 0; nt < 4; nt++) {
                    int cg = n0 + nw + nt * 8 + 2 * lc;
#pragma unroll
                    for (int q = 0; q < 2; q++) {
                        int col = cg + q;
                        if (col >= Nt) continue;
                        float v = acc[mt][nt][half * 2 + q];
                        if (bb) v += bb[col];
                        if (rr) v += rr[col];
                        Out[obase + col] = v;
                    }
                }
            }
        }
    }
}

// ------------------------- online logsumexp over vocab (single pass) ---------
__global__ void lse_kernel() {
    int p = blockIdx.x;
    const float* l = g_logits + (size_t)p * VOCAB_;
    int tid = threadIdx.x;
    float m = -INFINITY, s = 0.f;
    for (int v = tid; v < VOCAB_; v += 256) {
        float xv = l[v];
        if (xv > m) { s = s * expf(m - xv) + 1.f; m = xv; }
        else        { s += expf(xv - m); }
    }
    __shared__ float rm[256], rs[256];
    rm[tid] = m; rs[tid] = s;
    __syncthreads();
    for (int st = 128; st > 0; st >>= 1) {
        if (tid < st) {
            float m2 = rm[tid + st], s2 = rs[tid + st];
            float mm = fmaxf(rm[tid], m2);
            rs[tid] = rs[tid] * expf(rm[tid] - mm) + s2 * expf(m2 - mm);
            rm[tid] = mm;
        }
        __syncthreads();
    }
    if (tid == 0) g_lse[p] = rm[0] + logf(rs[0]);
}

// ------------------------- combine two experts per token ---------------------
__global__ void combine_kernel(float* __restrict__ out) {
    size_t idx = (size_t)blockIdx.x * blockDim.x + threadIdx.x;
    const size_t total = (size_t)S_ * VOCAB_;
    if (idx >= total) return;
    int s = (int)(idx / VOCAB_);
    int v = (int)(idx % VOCAB_);
    int p0 = 2 * s, p1 = 2 * s + 1;
    float a0 = g_logits[(size_t)p0 * VOCAB_ + v] + g_gate[p0] - g_lse[p0];
    float a1 = g_logits[(size_t)p1 * VOCAB_ + v] + g_gate[p1] - g_lse[p1];
    float m = fmaxf(a0, a1);
    out[idx] = m + logf(expf(a0 - m) + expf(a1 - m));
}

// ------------------------- launch -------------------------
extern "C" void kernel_launch(void* const* d_in, const int* in_sizes, int n_in,
                              void* d_out, int out_size) {
    const float *x = nullptr, *Wr = nullptr, *Wup = nullptr,
                *bup = nullptr, *Wdown = nullptr, *Wproj = nullptr;
    for (int i = 0; i < n_in; i++) {
        const float* p = (const float*)d_in[i];
        switch (in_sizes[i]) {
            case S_ * DIM_:            x     = p; break;
            case E_ * DIM_:            Wr    = p; break;
            case E_ * DFF2_ * DIM_:    Wup   = p; break;
            case E_ * DFF2_:           bup   = p; break;
            case E_ * DIM_ * DFF_:     Wdown = p; break;
            case E_ * VOCAB_ * DIM_:   Wproj = p; break;
        }
    }
    if (!x)     x     = (const float*)d_in[0];
    if (!Wr)    Wr    = (const float*)d_in[1];
    if (!Wup)   Wup   = (const float*)d_in[2];
    if (!bup)   bup   = (const float*)d_in[3];
    if (!Wdown) Wdown = (const float*)d_in[4];
    if (!Wproj) Wproj = (const float*)d_in[5];
    float* out = (float*)d_out;

    cudaFuncSetAttribute(gemm_tc_kernel<true>,
                         cudaFuncAttributeMaxDynamicSharedMemorySize, GEMM_SMEM);
    cudaFuncSetAttribute(gemm_tc_kernel<false>,
                         cudaFuncAttributeMaxDynamicSharedMemorySize, GEMM_SMEM);

    // 1) router + fused grouping
    router_kernel<<<S_, 256>>>(x, Wr);

    // 2) up + fused SwiGLU: g_h1 = h * gelu(gate)   (K=1024 -> F4)
    {
        dim3 grid((DFF2_ + TN - 1) / TN, (NPAIR + TM - 1) / TM, E_);
        gemm_tc_kernel<true><<<grid, NTHREADS, GEMM_SMEM>>>(x, Wup, bup, nullptr,
                                                            0, 1, 1, DIM_, DFF2_, 1);
    }
    // 3) down + residual: g_h2 = g_h1 @ Wdown[e]^T + x   (K=2730 -> F2)
    {
        dim3 grid((DIM_ + TN - 1) / TN, (NPAIR + TM - 1) / TM, E_);
        gemm_tc_kernel<false><<<grid, NTHREADS, GEMM_SMEM>>>(nullptr, Wdown, nullptr, x,
                                                             1, 2, 0, DFF_, DIM_, 0);
    }
    // 4) proj: g_logits = g_h2 @ Wproj[e]^T   <-- ncu capture slot (#4), F4
    {
        dim3 grid((VOCAB_ + TN - 1) / TN, (NPAIR + TM - 1) / TM, E_);
        gemm_tc_kernel<true><<<grid, NTHREADS, GEMM_SMEM>>>(nullptr, Wproj, nullptr, nullptr,
                                                            2, 3, 0, DIM_, VOCAB_, 0);
    }
    // 5) per-pair LSE, 6) combine
    lse_kernel<<<NPAIR, 256>>>();
    {
        size_t total = (size_t)S_ * VOCAB_;
        combine_kernel<<<(int)((total + 255) / 256), 256>>>(out);
    }
}